// round 6
// baseline (speedup 1.0000x reference)
#include <cuda_runtime.h>
#include <cstdint>

#define QQ 500
#define CDIM 256
#define QB 4
#define ROWS 32
#define MEMROWS 8500

// dynamic smem offsets (bytes)
#define OFF_EMB 0            // 256 c x 32 rows x 8B dup-pairs = 64 KB  (reused as h: 32 x 1KB)
#define OFF_W2T 65536        // 4 x 256 f32
#define OFF_SPT 69632        // 32 x float2
#define OFF_IDX 69888        // 32 x int4
#define OFF_WGT 70400        // 32 x float4
#define SMEM_TOTAL 70912

__device__ __forceinline__ unsigned long long ffma2(unsigned long long a,
                                                    unsigned long long b,
                                                    unsigned long long c) {
    unsigned long long d;
    asm("fma.rn.f32x2 %0, %1, %2, %3;" : "=l"(d) : "l"(a), "l"(b), "l"(c));
    return d;
}
__device__ __forceinline__ unsigned long long pack2(float lo, float hi) {
    unsigned long long r;
    asm("mov.b64 %0, {%1, %2};" : "=l"(r) : "f"(lo), "f"(hi));
    return r;
}
__device__ __forceinline__ void unpack2(unsigned long long v, float& lo, float& hi) {
    asm("mov.b64 {%0, %1}, %2;" : "=f"(lo), "=f"(hi) : "l"(v));
}
__device__ __forceinline__ float tanh_fast(float x) {
    float y; asm("tanh.approx.f32 %0, %1;" : "=f"(y) : "f"(x)); return y;
}

__global__ void __launch_bounds__(256, 3)
decoder_fused_kernel(const float* __restrict__ ref_polys,
                     const int*   __restrict__ ref_levels,
                     const float* __restrict__ memory,
                     const float* __restrict__ W1,
                     const float* __restrict__ b1,
                     const float* __restrict__ W2,
                     const float* __restrict__ b2,
                     float*       __restrict__ out)
{
    extern __shared__ __align__(16) char sb[];
    const int tid   = threadIdx.x;
    const int bid   = blockIdx.x;
    const int b     = bid / (QQ / QB);
    const int qbase = (bid % (QQ / QB)) * QB;

    // ---- Phase 1a: sampling points + bilinear corner setup (32 threads) ----
    if (tid < ROWS) {
        const int qi = tid >> 3;
        const int s  = tid & 7;
        const int q  = qbase + qi;
        const float* rp = ref_polys + (size_t)(b * QQ + q) * 8;
        const float lam = (float)s * (1.0f / 7.0f);
        const float sx = 2.0f * ((((rp[0] * lam + rp[1]) * lam + rp[2]) * lam + rp[3]) - 0.5f);
        const float sy = 2.0f * ((((rp[4] * lam + rp[5]) * lam + rp[6]) * lam + rp[7]) - 0.5f);
        ((float2*)(sb + OFF_SPT))[tid] = make_float2(sx, sy);

        const int lvl = ref_levels[b * QQ + q];
        const int hs_tab[4] = {80, 40, 20, 10};
        const int st_tab[4] = {0, 6400, 8000, 8400};
        const int W  = hs_tab[lvl];
        const int st = st_tab[lvl];

        const float gx = (sx + 1.0f) * 0.5f * (float)W - 0.5f;
        const float gy = (sy + 1.0f) * 0.5f * (float)W - 0.5f;
        const float x0f = floorf(gx), y0f = floorf(gy);
        const float fx = gx - x0f, fy = gy - y0f;
        const int x0 = (int)x0f, y0 = (int)y0f;
        const int base = b * MEMROWS + st;
        int4 ix; float4 wv;
        int* ixp = (int*)&ix; float* wvp = (float*)&wv;
        #pragma unroll
        for (int k = 0; k < 4; k++) {
            const int xi = x0 + (k & 1);
            const int yi = y0 + (k >> 1);
            const bool v = (xi >= 0) && (xi < W) && (yi >= 0) && (yi < W);
            ixp[k] = v ? (base + yi * W + xi) : -1;
            const float wx = (k & 1) ? fx : 1.0f - fx;
            const float wy = (k >> 1) ? fy : 1.0f - fy;
            wvp[k] = wx * wy;
        }
        ((int4*)(sb + OFF_IDX))[tid] = ix;
        ((float4*)(sb + OFF_WGT))[tid] = wv;
    }
    // ---- Phase 1b: W2 transpose into smem ----
    #pragma unroll
    for (int i = tid; i < 4 * CDIM; i += 256)
        ((float*)(sb + OFF_W2T))[(i & 3) * 256 + (i >> 2)] = W2[i];
    __syncthreads();

    // ---- Phase 2: bilinear gather -> DUPLICATED bf pairs in smem (thread = channel c) ----
    // store (e0,e0,e1,e1) per row-pair r2, swizzled slot = r2 ^ (c & 15)
    {
        const int c = tid;
        const uint32_t cbase = (uint32_t)c << 8;     // c * 256 bytes
        const uint32_t csw   = (uint32_t)(c & 15);
        #pragma unroll 4
        for (int r2 = 0; r2 < 16; r2++) {
            float e[2];
            #pragma unroll
            for (int rr = 0; rr < 2; rr++) {
                const int r = 2 * r2 + rr;
                const int4   ix = ((const int4*)(sb + OFF_IDX))[r];
                const float4 wv = ((const float4*)(sb + OFF_WGT))[r];
                float acc = 0.0f;
                if (ix.x >= 0) acc += wv.x * __ldg(memory + (size_t)ix.x * CDIM + c);
                if (ix.y >= 0) acc += wv.y * __ldg(memory + (size_t)ix.y * CDIM + c);
                if (ix.z >= 0) acc += wv.z * __ldg(memory + (size_t)ix.z * CDIM + c);
                if (ix.w >= 0) acc += wv.w * __ldg(memory + (size_t)ix.w * CDIM + c);
                e[rr] = acc;
            }
            *(float4*)(sb + OFF_EMB + cbase + (((uint32_t)r2 ^ csw) << 4)) =
                make_float4(e[0], e[0], e[1], e[1]);
        }
    }
    __syncthreads();

    // ---- Phase 3: layer-1 GEMM. Thread tile = 8 rows x 4 cols.
    //      acc lanes = column pair (j, j+1): weight operand is a natural LDG.128 pair,
    //      emb operand is the pre-duplicated (e,e) pair. Zero per-iter lane-dup MOVs. ----
    {
        const int lane = tid & 31;
        const int wid  = tid >> 5;
        const int rb   = lane & 3;                       // row block: rows rb*8 .. rb*8+7
        const int cb   = (lane >> 2) + (wid << 3);       // 0..63
        const int j0   = cb << 2;

        const float4 b1v = __ldg((const float4*)(b1 + j0));
        unsigned long long acc[8][2];
        #pragma unroll
        for (int r = 0; r < 8; r++) {
            acc[r][0] = pack2(b1v.x, b1v.y);
            acc[r][1] = pack2(b1v.z, b1v.w);
        }

        const float* w1p = W1 + j0;
        for (int c0 = 0; c0 < CDIM; c0 += 16) {
            #pragma unroll
            for (int cc = 0; cc < 16; cc++) {
                const int c = c0 + cc;
                const ulonglong2 wv = *(const ulonglong2*)(w1p + (size_t)c * CDIM);
                // slot = (rb*4 + ch) ^ cc ; split into independent bit fields:
                const char* ebase = sb + OFF_EMB + ((uint32_t)c << 8)
                                  + ((uint32_t)(rb ^ (cc >> 2)) << 6);
                #pragma unroll
                for (int ch = 0; ch < 4; ch++) {
                    const ulonglong2 ev =
                        *(const ulonglong2*)(ebase + ((uint32_t)(ch ^ (cc & 3)) << 4));
                    acc[2 * ch    ][0] = ffma2(ev.x, wv.x, acc[2 * ch    ][0]);
                    acc[2 * ch    ][1] = ffma2(ev.x, wv.y, acc[2 * ch    ][1]);
                    acc[2 * ch + 1][0] = ffma2(ev.y, wv.x, acc[2 * ch + 1][0]);
                    acc[2 * ch + 1][1] = ffma2(ev.y, wv.y, acc[2 * ch + 1][1]);
                }
            }
        }

        __syncthreads();   // all emb reads done before buffer is reused as h

        #pragma unroll
        for (int r = 0; r < 8; r++) {
            float a0, a1, a2, a3;
            unpack2(acc[r][0], a0, a1);
            unpack2(acc[r][1], a2, a3);
            const int row = rb * 8 + r;
            const float4 hv = make_float4(tanh_fast(a0), tanh_fast(a1),
                                          tanh_fast(a2), tanh_fast(a3));
            *(float4*)(sb + ((uint32_t)row << 10)
                          + (((uint32_t)(j0 << 2)) ^ ((uint32_t)(row & 7) << 4))) = hv;
        }
    }
    __syncthreads();

    // ---- Phase 4: layer 2 + tanh epilogue (all 256 threads; half-sums + shfl) ----
    {
        const int r    = tid >> 3;         // 0..31
        const int p    = (tid >> 1) & 3;   // 0..3
        const int half = tid & 1;
        const uint32_t sw = (uint32_t)(r & 7) << 4;
        const char* hrow  = sb + ((uint32_t)r << 10);
        const char* w2p   = sb + OFF_W2T + p * 1024;

        unsigned long long acc2 = 0;
        const int jb0 = half << 9;
        #pragma unroll 8
        for (int g = 0; g < 32; g++) {
            const uint32_t off = (uint32_t)(jb0 + (g << 4));
            const float4 hv = *(const float4*)(hrow + (off ^ sw));
            const float4 wv = *(const float4*)(w2p + off);
            acc2 = ffma2(pack2(hv.x, hv.y), pack2(wv.x, wv.y), acc2);
            acc2 = ffma2(pack2(hv.z, hv.w), pack2(wv.z, wv.w), acc2);
        }
        float lo, hi;
        unpack2(acc2, lo, hi);
        float sum = lo + hi;
        sum += __shfl_xor_sync(0xffffffffu, sum, 1);
        if (half == 0) {
            sum += __ldg(b2 + p);
            const float off = 0.077f * tanh_fast(sum);
            const float2 spt = ((const float2*)(sb + OFF_SPT))[r];
            const int qi = r >> 3, s = r & 7;
            const int q = qbase + qi;
            out[(size_t)(b * QQ + q) * 32 + s * 4 + p] = off + ((p & 1) ? spt.y : spt.x);
        }
    }
}

extern "C" void kernel_launch(void* const* d_in, const int* in_sizes, int n_in,
                              void* d_out, int out_size)
{
    const float* ref_polys  = (const float*)d_in[0];
    const int*   ref_levels = (const int*)  d_in[1];
    const float* memory     = (const float*)d_in[2];
    const float* W1         = (const float*)d_in[3];
    const float* b1         = (const float*)d_in[4];
    const float* W2         = (const float*)d_in[5];
    const float* b2         = (const float*)d_in[6];
    float* out = (float*)d_out;

    cudaFuncSetAttribute(decoder_fused_kernel,
                         cudaFuncAttributeMaxDynamicSharedMemorySize, SMEM_TOTAL);

    const int blocks = 8 * QQ / QB;   // 1000
    decoder_fused_kernel<<<blocks, 256, SMEM_TOTAL>>>(ref_polys, ref_levels, memory,
                                                      W1, b1, W2, b2, out);
}

// round 7
// speedup vs baseline: 4.3594x; 4.3594x over previous
#include <cuda_runtime.h>
#include <cstdint>

#define QQ 500
#define CDIM 256
#define ROWS 64              // rows per CTA (8 queries x 8 samples, flattened globally)
#define NCTAS 500            // 32000 / 64
#define MEMROWS 8500

// dynamic smem offsets (bytes)
#define OFF_A   0                    // emb rows 0..31:  c*128, 32 KB   (reused as h rows 0..31)
#define OFF_B   (32768 + 16)         // emb rows 32..63: c*128, 32 KB, +16B bank skew (h rows 32..63)
#define OFF_W2T 65568                // 4 x 260 f32 (1040 B stride)
#define OFF_SPT 69728                // 64 x float2
#define OFF_IDX 70240                // 64 x int4
#define OFF_WGT 71264                // 64 x float4
#define SMEM_TOTAL 72288

__device__ __forceinline__ unsigned long long ffma2(unsigned long long a,
                                                    unsigned long long b,
                                                    unsigned long long c) {
    unsigned long long d;
    asm("fma.rn.f32x2 %0, %1, %2, %3;" : "=l"(d) : "l"(a), "l"(b), "l"(c));
    return d;
}
__device__ __forceinline__ unsigned long long pack2(float lo, float hi) {
    unsigned long long r;
    asm("mov.b64 %0, {%1, %2};" : "=l"(r) : "f"(lo), "f"(hi));
    return r;
}
__device__ __forceinline__ void unpack2(unsigned long long v, float& lo, float& hi) {
    asm("mov.b64 {%0, %1}, %2;" : "=f"(lo), "=f"(hi) : "l"(v));
}
__device__ __forceinline__ float tanh_fast(float x) {
    float y; asm("tanh.approx.f32 %0, %1;" : "=f"(y) : "f"(x)); return y;
}

__global__ void __launch_bounds__(256, 2)
decoder_fused_kernel(const float* __restrict__ ref_polys,
                     const int*   __restrict__ ref_levels,
                     const float* __restrict__ memory,
                     const float* __restrict__ W1,
                     const float* __restrict__ b1,
                     const float* __restrict__ W2,
                     const float* __restrict__ b2,
                     float*       __restrict__ out)
{
    extern __shared__ __align__(16) char sb[];
    const int tid = threadIdx.x;
    const int bid = blockIdx.x;

    // ---- Phase 1a: per-row sampling point + bilinear corner setup (64 threads) ----
    if (tid < ROWS) {
        const int gr = bid * ROWS + tid;        // global row, (bq, s) flattened
        const int bq = gr >> 3;
        const int s  = gr & 7;
        const float* rp = ref_polys + (size_t)bq * 8;
        const float lam = (float)s * (1.0f / 7.0f);
        const float sx = 2.0f * ((((rp[0] * lam + rp[1]) * lam + rp[2]) * lam + rp[3]) - 0.5f);
        const float sy = 2.0f * ((((rp[4] * lam + rp[5]) * lam + rp[6]) * lam + rp[7]) - 0.5f);
        ((float2*)(sb + OFF_SPT))[tid] = make_float2(sx, sy);

        const int lvl = ref_levels[bq];
        const int hs_tab[4] = {80, 40, 20, 10};
        const int st_tab[4] = {0, 6400, 8000, 8400};
        const int W  = hs_tab[lvl];
        const int st = st_tab[lvl];
        const int b  = bq / QQ;

        const float gx = (sx + 1.0f) * 0.5f * (float)W - 0.5f;
        const float gy = (sy + 1.0f) * 0.5f * (float)W - 0.5f;
        const float x0f = floorf(gx), y0f = floorf(gy);
        const float fx = gx - x0f, fy = gy - y0f;
        const int x0 = (int)x0f, y0 = (int)y0f;
        const int base = b * MEMROWS + st;
        int4 ix; float4 wv;
        int* ixp = (int*)&ix; float* wvp = (float*)&wv;
        #pragma unroll
        for (int k = 0; k < 4; k++) {
            const int xi = x0 + (k & 1);
            const int yi = y0 + (k >> 1);
            const bool v = (xi >= 0) && (xi < W) && (yi >= 0) && (yi < W);
            ixp[k] = v ? (base + yi * W + xi) : -1;
            const float wx = (k & 1) ? fx : 1.0f - fx;
            const float wy = (k >> 1) ? fy : 1.0f - fy;
            wvp[k] = wx * wy;
        }
        ((int4*)(sb + OFF_IDX))[tid] = ix;
        ((float4*)(sb + OFF_WGT))[tid] = wv;
    }
    // ---- Phase 1b: W2^T into smem, 1040-byte row stride ----
    #pragma unroll
    for (int i = tid; i < 4 * CDIM; i += 256)
        *(float*)(sb + OFF_W2T + (i & 3) * 1040 + (i >> 2) * 4) = W2[i];
    __syncthreads();

    // ---- Phase 2: bilinear gather -> emb halves A/B (thread = channel c) ----
    {
        const int c = tid;
        const uint32_t csw = (uint32_t)(c & 7);
        #pragma unroll 2
        for (int r4 = 0; r4 < 16; r4++) {           // 4 rows per float4 store
            float4 buf;
            float* bf = (float*)&buf;
            #pragma unroll
            for (int rr = 0; rr < 4; rr++) {
                const int r = r4 * 4 + rr;
                const int4   ix = ((const int4*)(sb + OFF_IDX))[r];
                const float4 wv = ((const float4*)(sb + OFF_WGT))[r];
                float acc = 0.0f;
                if (ix.x >= 0) acc += wv.x * __ldg(memory + (size_t)ix.x * CDIM + c);
                if (ix.y >= 0) acc += wv.y * __ldg(memory + (size_t)ix.y * CDIM + c);
                if (ix.z >= 0) acc += wv.z * __ldg(memory + (size_t)ix.z * CDIM + c);
                if (ix.w >= 0) acc += wv.w * __ldg(memory + (size_t)ix.w * CDIM + c);
                bf[rr] = acc;
            }
            const uint32_t half = (uint32_t)(r4 >> 3);
            const uint32_t gsl  = ((uint32_t)(r4 & 7)) ^ csw;
            *(float4*)(sb + half * (uint32_t)OFF_B + ((uint32_t)c << 7) + (gsl << 4)) = buf;
        }
    }
    __syncthreads();

    // ---- Phase 3: layer-1 GEMM, thread tile = 8 rows x 8 cols ----
    {
        const int lane = tid & 31;
        const int wid  = tid >> 5;
        const int rb   = lane & 7;                  // rows rb*8 .. rb*8+7
        const int e    = lane >> 3;                 // 0..3
        const int cb   = wid * 4 + e;               // 0..31
        const int j0   = cb * 8;

        const float4 b1a = __ldg((const float4*)(b1 + j0));
        const float4 b1b = __ldg((const float4*)(b1 + j0 + 4));
        unsigned long long acc[4][8];               // [rowpair][col]
        #pragma unroll
        for (int rp = 0; rp < 4; rp++) {
            acc[rp][0] = pack2(b1a.x, b1a.x); acc[rp][1] = pack2(b1a.y, b1a.y);
            acc[rp][2] = pack2(b1a.z, b1a.z); acc[rp][3] = pack2(b1a.w, b1a.w);
            acc[rp][4] = pack2(b1b.x, b1b.x); acc[rp][5] = pack2(b1b.y, b1b.y);
            acc[rp][6] = pack2(b1b.z, b1b.z); acc[rp][7] = pack2(b1b.w, b1b.w);
        }
        // NOTE: acc lane pair = (row 2rp+?, ...) — see FFMA2 mapping below:
        // acc[rp][col] lanes = rows (rb*8+2rp, rb*8+2rp+1) for column j0+col.
        // bias must be (b1j, b1j) in both lanes: fixed above (same value both lanes). OK.

        const char* ebase = sb + (uint32_t)(rb >> 2) * (uint32_t)OFF_B;
        const uint32_t rbf = ((uint32_t)(rb & 3)) << 5;
        const float* w1p = W1 + j0;

        for (int c0 = 0; c0 < CDIM; c0 += 8) {
            #pragma unroll
            for (int cc = 0; cc < 8; cc++) {
                const int c = c0 + cc;
                const float4 wA = __ldg((const float4*)(w1p + (size_t)c * CDIM));
                const float4 wB = __ldg((const float4*)(w1p + (size_t)c * CDIM + 4));
                const uint32_t v0 = rbf ^ ((uint32_t)cc << 4);
                const char* ep = ebase + ((uint32_t)c << 7);
                const ulonglong2 eA = *(const ulonglong2*)(ep + v0);
                const ulonglong2 eB = *(const ulonglong2*)(ep + (v0 ^ 16u));
                const unsigned long long w0 = pack2(wA.x, wA.x);
                const unsigned long long w1v = pack2(wA.y, wA.y);
                const unsigned long long w2v = pack2(wA.z, wA.z);
                const unsigned long long w3 = pack2(wA.w, wA.w);
                const unsigned long long w4 = pack2(wB.x, wB.x);
                const unsigned long long w5 = pack2(wB.y, wB.y);
                const unsigned long long w6 = pack2(wB.z, wB.z);
                const unsigned long long w7 = pack2(wB.w, wB.w);
                acc[0][0] = ffma2(eA.x, w0, acc[0][0]); acc[0][1] = ffma2(eA.x, w1v, acc[0][1]);
                acc[0][2] = ffma2(eA.x, w2v, acc[0][2]); acc[0][3] = ffma2(eA.x, w3, acc[0][3]);
                acc[0][4] = ffma2(eA.x, w4, acc[0][4]); acc[0][5] = ffma2(eA.x, w5, acc[0][5]);
                acc[0][6] = ffma2(eA.x, w6, acc[0][6]); acc[0][7] = ffma2(eA.x, w7, acc[0][7]);
                acc[1][0] = ffma2(eA.y, w0, acc[1][0]); acc[1][1] = ffma2(eA.y, w1v, acc[1][1]);
                acc[1][2] = ffma2(eA.y, w2v, acc[1][2]); acc[1][3] = ffma2(eA.y, w3, acc[1][3]);
                acc[1][4] = ffma2(eA.y, w4, acc[1][4]); acc[1][5] = ffma2(eA.y, w5, acc[1][5]);
                acc[1][6] = ffma2(eA.y, w6, acc[1][6]); acc[1][7] = ffma2(eA.y, w7, acc[1][7]);
                acc[2][0] = ffma2(eB.x, w0, acc[2][0]); acc[2][1] = ffma2(eB.x, w1v, acc[2][1]);
                acc[2][2] = ffma2(eB.x, w2v, acc[2][2]); acc[2][3] = ffma2(eB.x, w3, acc[2][3]);
                acc[2][4] = ffma2(eB.x, w4, acc[2][4]); acc[2][5] = ffma2(eB.x, w5, acc[2][5]);
                acc[2][6] = ffma2(eB.x, w6, acc[2][6]); acc[2][7] = ffma2(eB.x, w7, acc[2][7]);
                acc[3][0] = ffma2(eB.y, w0, acc[3][0]); acc[3][1] = ffma2(eB.y, w1v, acc[3][1]);
                acc[3][2] = ffma2(eB.y, w2v, acc[3][2]); acc[3][3] = ffma2(eB.y, w3, acc[3][3]);
                acc[3][4] = ffma2(eB.y, w4, acc[3][4]); acc[3][5] = ffma2(eB.y, w5, acc[3][5]);
                acc[3][6] = ffma2(eB.y, w6, acc[3][6]); acc[3][7] = ffma2(eB.y, w7, acc[3][7]);
            }
        }

        __syncthreads();   // emb reads complete before buffer reuse as h

        // tanh + store h: rows rb*8+2rp{,+1}, cols j0..j0+7
        #pragma unroll
        for (int rp = 0; rp < 4; rp++) {
            float lo[8], hi[8];
            #pragma unroll
            for (int k = 0; k < 8; k++) unpack2(acc[rp][k], lo[k], hi[k]);
            #pragma unroll
            for (int t = 0; t < 2; t++) {
                const float* v = t ? hi : lo;
                const int row = rb * 8 + 2 * rp + t;
                char* hb = sb + (((uint32_t)row & 31u) << 10)
                              + ((uint32_t)(row >> 5)) * (uint32_t)OFF_B;
                const uint32_t sw = ((uint32_t)(row & 7)) << 4;
                *(float4*)(hb + (((uint32_t)(j0 * 4)) ^ sw)) =
                    make_float4(tanh_fast(v[0]), tanh_fast(v[1]),
                                tanh_fast(v[2]), tanh_fast(v[3]));
                *(float4*)(hb + (((uint32_t)(j0 * 4 + 16)) ^ sw)) =
                    make_float4(tanh_fast(v[4]), tanh_fast(v[5]),
                                tanh_fast(v[6]), tanh_fast(v[7]));
            }
        }
    }
    __syncthreads();

    // ---- Phase 4: layer 2 + tanh epilogue (thread = (row, p)) ----
    {
        const int r = tid >> 2;            // 0..63
        const int p = tid & 3;             // 0..3
        const char* hrow = sb + (((uint32_t)r & 31u) << 10)
                              + ((uint32_t)(r >> 5)) * (uint32_t)OFF_B;
        const uint32_t sw = ((uint32_t)(r & 7)) << 4;
        const char* w2p = sb + OFF_W2T + p * 1040;

        unsigned long long a0 = 0, a1 = 0;
        #pragma unroll 8
        for (int g = 0; g < 64; g++) {
            const uint32_t off = (uint32_t)g << 4;
            const ulonglong2 hv = *(const ulonglong2*)(hrow + (off ^ sw));
            const ulonglong2 wv = *(const ulonglong2*)(w2p + off);
            a0 = ffma2(hv.x, wv.x, a0);
            a1 = ffma2(hv.y, wv.y, a1);
        }
        float l0, h0, l1, h1;
        unpack2(a0, l0, h0);
        unpack2(a1, l1, h1);
        float sum = (l0 + h0) + (l1 + h1) + __ldg(b2 + p);
        const float off = 0.077f * tanh_fast(sum);
        const float2 spt = ((const float2*)(sb + OFF_SPT))[r];
        const int gr = bid * ROWS + r;
        out[(size_t)gr * 4 + p] = off + ((p & 1) ? spt.y : spt.x);
    }
}

extern "C" void kernel_launch(void* const* d_in, const int* in_sizes, int n_in,
                              void* d_out, int out_size)
{
    const float* ref_polys  = (const float*)d_in[0];
    const int*   ref_levels = (const int*)  d_in[1];
    const float* memory     = (const float*)d_in[2];
    const float* W1         = (const float*)d_in[3];
    const float* b1         = (const float*)d_in[4];
    const float* W2         = (const float*)d_in[5];
    const float* b2         = (const float*)d_in[6];
    float* out = (float*)d_out;

    cudaFuncSetAttribute(decoder_fused_kernel,
                         cudaFuncAttributeMaxDynamicSharedMemorySize, SMEM_TOTAL);

    decoder_fused_kernel<<<NCTAS, 256, SMEM_TOTAL>>>(ref_polys, ref_levels, memory,
                                                     W1, b1, W2, b2, out);
}